// round 11
// baseline (speedup 1.0000x reference)
#include <cuda_runtime.h>
#include <cstdint>

#define B_ 8
#define S_ 4096
#define H_ 1024

typedef unsigned long long ull;

// ---------------- scratch (no allocations allowed) ----------------
__device__ int      g_pos[B_ * S_];     // compacted original positions per row
__device__ int      g_nb[B_];           // kept count per row
__device__ int      g_tokens[B_];       // top-k count per row
__device__ unsigned g_smax[B_ * S_];    // encoded (order-preserving) max logits per slot

// ---------------- helpers ----------------
__device__ __forceinline__ unsigned enc_f(float f) {
    unsigned u = __float_as_uint(f);
    return (u & 0x80000000u) ? ~u : (u | 0x80000000u);
}
__device__ __forceinline__ float dec_f(unsigned u) {
    return __uint_as_float((u & 0x80000000u) ? (u & 0x7FFFFFFFu) : ~u);
}
__device__ __forceinline__ ull fma2(ull a, ull b, ull c) {
    ull d;
    asm("fma.rn.f32x2 %0, %1, %2, %3;" : "=l"(d) : "l"(a), "l"(b), "l"(c));
    return d;
}
__device__ __forceinline__ ull pack2(float x) {
    ull r;
    asm("mov.b64 %0, {%1, %1};" : "=l"(r) : "f"(x));
    return r;
}

// ---------------- kernel 1: per-row compaction metadata ----------------
// 8 blocks x 1024 threads; each thread owns 4 consecutive positions.
__global__ __launch_bounds__(1024) void prep_kernel(
    const float* __restrict__ prev, const float* __restrict__ amask,
    float* __restrict__ out_mask)
{
    int b = blockIdx.x;
    int t = threadIdx.x;
    const float* pm = prev + b * S_;
    const float* am = amask + b * S_;

    int base_p = t * 4;
    float pv[4];
    int kept[4];
    int local = 0, lz = 0;
#pragma unroll
    for (int i = 0; i < 4; i++) {
        float v = pm[base_p + i];
        pv[i] = v;
        int k = (v > 0.5f) ? 1 : 0;
        kept[i] = k;
        local += k;
        lz += (k && (am[base_p + i] == 0.0f)) ? 1 : 0;
    }

    int lane = t & 31, warp = t >> 5;
    const unsigned FULL = 0xFFFFFFFFu;
    // warp-inclusive scan of per-thread kept counts
    int inc = local;
#pragma unroll
    for (int o = 1; o < 32; o <<= 1) {
        int n = __shfl_up_sync(FULL, inc, o);
        if (lane >= o) inc += n;
    }
    // warp sum of zero-mask counts
    int wz = lz;
#pragma unroll
    for (int o = 16; o > 0; o >>= 1) wz += __shfl_xor_sync(FULL, wz, o);

    __shared__ int wsum[32], wzsum[32], wbase[32];
    __shared__ int s_tot, s_cz;
    if (lane == 31) wsum[warp] = inc;
    if (lane == 0)  wzsum[warp] = wz;
    __syncthreads();
    if (t < 32) {
        int v = wsum[t];
        int e = v;
#pragma unroll
        for (int o = 1; o < 32; o <<= 1) {
            int n = __shfl_up_sync(FULL, e, o);
            if (t >= o) e += n;
        }
        wbase[t] = e - v;
        if (t == 31) s_tot = e;
        int z = wzsum[t];
#pragma unroll
        for (int o = 16; o > 0; o >>= 1) z += __shfl_xor_sync(FULL, z, o);
        if (t == 0) s_cz = z;
    }
    __syncthreads();

    int slot = wbase[warp] + inc - local;  // exclusive prefix for this thread
#pragma unroll
    for (int i = 0; i < 4; i++) {
        int p = base_p + i;
        if (kept[i]) { g_pos[b * S_ + slot] = p; slot++; }
        // kept positions reset to 0 (topk scatters 1s later),
        // non-kept positions keep previous_mask value
        out_mask[b * S_ + p] = kept[i] ? 0.0f : pv[i];
        g_smax[b * S_ + p] = 0u;  // encoded floor
    }
    if (t == 0) {
        g_nb[b] = s_tot;
        float cz = (float)s_cz;
        int tk = (int)(cz * 0.8f);  // match jnp float32 * 0.8 then int32 trunc
        if (tk < 1) tk = 1;
        g_tokens[b] = tk;
    }
}

// ---------------- kernel 2: new_ret = hidden_states ----------------
__global__ void copy_kernel(const float4* __restrict__ src, float4* __restrict__ dst, int n4)
{
    int i = blockIdx.x * blockDim.x + threadIdx.x;
    int stride = gridDim.x * blockDim.x;
    for (; i < n4; i += stride) dst[i] = src[i];
}

// ---------------- kernel 3: gathered GEMM + row-max (f32x2 packed FMAs) ----------------
// Block tile: TM=64 tokens x TN=128 columns, K chunks of 16, 256 threads.
// Thread tile: 8 m (4 f32x2 pairs) x 4 n = 32 MACs per k via 16 FFMA2.
#define TM 64
#define TN 128
#define TK 16

__global__ __launch_bounds__(256) void gemm_kernel(
    const float* __restrict__ hmat, const float* __restrict__ W,
    const float* __restrict__ bias)
{
    int b = blockIdx.y;
    int nb = g_nb[b];
    int j0 = blockIdx.x * TM;
    if (j0 >= nb) return;
    int n0 = blockIdx.z * TN;

    int tid = threadIdx.x;
    int tx = tid & 31, ty = tid >> 5;

    __shared__ float As[2][TK][TM];
    __shared__ float Bs[2][TK][TN];
    __shared__ const float* rowptr_s[TM];

    if (tid < TM) {
        int j = j0 + tid;
        int jc = (j < nb) ? j : (nb - 1);
        if (jc < 0) jc = 0;
        int p = g_pos[b * S_ + jc];
        rowptr_s[tid] = hmat + ((size_t)b * S_ + (size_t)p) * H_;
    }
    __syncthreads();

    int am  = tid & 63;   // A row within tile
    int akq = tid >> 6;   // A k-quad (0..3)
    const float* wbase = W + n0;

    ull acc[4][4];
#pragma unroll
    for (int i = 0; i < 4; i++)
#pragma unroll
        for (int j = 0; j < 4; j++) acc[i][j] = 0ull;

    auto load_stage = [&](int stage, int kk) {
        float4 av = *(const float4*)(rowptr_s[am] + kk + akq * 4);
        As[stage][akq * 4 + 0][am] = av.x;
        As[stage][akq * 4 + 1][am] = av.y;
        As[stage][akq * 4 + 2][am] = av.z;
        As[stage][akq * 4 + 3][am] = av.w;
#pragma unroll
        for (int it = 0; it < 2; it++) {
            int idx = it * 256 + tid;
            int bk = idx >> 5;          // 0..15
            int bn = (idx & 31) * 4;    // 0..124
            float4 wv = *(const float4*)(wbase + (size_t)(kk + bk) * H_ + bn);
            *(float4*)&Bs[stage][bk][bn] = wv;
        }
    };

    load_stage(0, 0);
    __syncthreads();

#pragma unroll 1
    for (int kt = 0; kt < H_ / TK; kt++) {
        int cur = kt & 1;
        if (kt + 1 < H_ / TK) load_stage(cur ^ 1, (kt + 1) * TK);
#pragma unroll
        for (int k = 0; k < TK; k++) {
            const ull* ap = (const ull*)&As[cur][k][ty * 8];  // 4 natural (m,m+1) pairs
            ull a2_0 = ap[0], a2_1 = ap[1], a2_2 = ap[2], a2_3 = ap[3];
            float4 bw = *(const float4*)&Bs[cur][k][tx * 4];
            ull b0 = pack2(bw.x), b1 = pack2(bw.y), b2 = pack2(bw.z), b3 = pack2(bw.w);
            acc[0][0] = fma2(a2_0, b0, acc[0][0]);
            acc[1][0] = fma2(a2_1, b0, acc[1][0]);
            acc[2][0] = fma2(a2_2, b0, acc[2][0]);
            acc[3][0] = fma2(a2_3, b0, acc[3][0]);
            acc[0][1] = fma2(a2_0, b1, acc[0][1]);
            acc[1][1] = fma2(a2_1, b1, acc[1][1]);
            acc[2][1] = fma2(a2_2, b1, acc[2][1]);
            acc[3][1] = fma2(a2_3, b1, acc[3][1]);
            acc[0][2] = fma2(a2_0, b2, acc[0][2]);
            acc[1][2] = fma2(a2_1, b2, acc[1][2]);
            acc[2][2] = fma2(a2_2, b2, acc[2][2]);
            acc[3][2] = fma2(a2_3, b2, acc[3][2]);
            acc[0][3] = fma2(a2_0, b3, acc[0][3]);
            acc[1][3] = fma2(a2_1, b3, acc[1][3]);
            acc[2][3] = fma2(a2_2, b3, acc[2][3]);
            acc[3][3] = fma2(a2_3, b3, acc[3][3]);
        }
        __syncthreads();
    }

    // epilogue: add bias, per-row max over this block's 128 columns
    float rmax[8];
#pragma unroll
    for (int i = 0; i < 8; i++) rmax[i] = -3.0e38f;
#pragma unroll
    for (int jn = 0; jn < 4; jn++) {
        float bn = bias[n0 + tx * 4 + jn];
#pragma unroll
        for (int mi = 0; mi < 4; mi++) {
            float lo = __uint_as_float((unsigned)(acc[mi][jn] & 0xFFFFFFFFull)) + bn;
            float hi = __uint_as_float((unsigned)(acc[mi][jn] >> 32)) + bn;
            rmax[2 * mi]     = fmaxf(rmax[2 * mi], lo);
            rmax[2 * mi + 1] = fmaxf(rmax[2 * mi + 1], hi);
        }
    }
#pragma unroll
    for (int i = 0; i < 8; i++) {
        float v = rmax[i];
#pragma unroll
        for (int o = 16; o > 0; o >>= 1)
            v = fmaxf(v, __shfl_xor_sync(0xFFFFFFFFu, v, o));
        if (tx == 0) {
            int j = j0 + ty * 8 + i;
            if (j < nb) atomicMax(&g_smax[b * S_ + j], enc_f(v));
        }
    }
}

// ---------------- kernel 4: per-row stable top-k via bitonic sort ----------------
__global__ __launch_bounds__(1024) void topk_kernel(
    const float* __restrict__ amask, float* __restrict__ out_mask)
{
    int b = blockIdx.x;
    __shared__ ull key[S_];
    int nb = g_nb[b];
    int tk = g_tokens[b];

    for (int j = threadIdx.x; j < S_; j += 1024) {
        ull kv = 0ull;
        if (j < nb) {
            float s = dec_f(g_smax[b * S_ + j]);
            int p = g_pos[b * S_ + j];
            float a = amask[b * S_ + p];
            float sv = s + a * 100.0f + a;  // scores + sub_a (a==0 for kept rows anyway)
            kv = ((ull)enc_f(sv) << 32) | (ull)(0xFFFFFFFFu - (unsigned)j);
        }
        key[j] = kv;
    }
    __syncthreads();

    // full descending bitonic sort; key = (score asc-encoded, ~index) so ties
    // break toward the smaller slot index — identical to stable argsort(-s).
    for (int k = 2; k <= S_; k <<= 1) {
        for (int jj = k >> 1; jj > 0; jj >>= 1) {
            for (int i = threadIdx.x; i < S_; i += 1024) {
                int ixj = i ^ jj;
                if (ixj > i) {
                    bool desc = ((i & k) == 0);
                    ull A = key[i], Bv = key[ixj];
                    bool sw = desc ? (A < Bv) : (A > Bv);
                    if (sw) { key[i] = Bv; key[ixj] = A; }
                }
            }
            __syncthreads();
        }
    }

    for (int r = threadIdx.x; r < tk; r += 1024) {
        unsigned j = 0xFFFFFFFFu - (unsigned)(key[r] & 0xFFFFFFFFull);
        int p = g_pos[b * S_ + (int)j];
        out_mask[b * S_ + p] = 1.0f;
    }
}

// ---------------- launch ----------------
extern "C" void kernel_launch(void* const* d_in, const int* in_sizes, int n_in,
                              void* d_out, int out_size)
{
    (void)in_sizes; (void)n_in; (void)out_size;
    const float* hidden = (const float*)d_in[0];
    const float* amask  = (const float*)d_in[1];
    const float* prev   = (const float*)d_in[2];
    const float* W      = (const float*)d_in[3];
    const float* bias   = (const float*)d_in[4];

    float* out_ret  = (float*)d_out;
    float* out_mask = out_ret + (size_t)B_ * S_ * H_;

    prep_kernel<<<B_, 1024>>>(prev, amask, out_mask);

    int n4 = B_ * S_ * H_ / 4;
    copy_kernel<<<4096, 512>>>((const float4*)hidden, (float4*)out_ret, n4);

    dim3 ggrid(S_ / TM, B_, H_ / TN);
    gemm_kernel<<<ggrid, 256>>>(hidden, W, bias);

    topk_kernel<<<B_, 1024>>>(amask, out_mask);
}

// round 12
// speedup vs baseline: 1.0251x; 1.0251x over previous
#include <cuda_runtime.h>
#include <cstdint>

#define B_ 8
#define S_ 4096
#define H_ 1024

typedef unsigned long long ull;

// ---------------- scratch (no allocations allowed) ----------------
__device__ int      g_pos[B_ * S_];
__device__ int      g_nb[B_];
__device__ int      g_tokens[B_];
__device__ unsigned g_smax[B_ * S_];

// ---------------- helpers ----------------
__device__ __forceinline__ unsigned enc_f(float f) {
    unsigned u = __float_as_uint(f);
    return (u & 0x80000000u) ? ~u : (u | 0x80000000u);
}
__device__ __forceinline__ float dec_f(unsigned u) {
    return __uint_as_float((u & 0x80000000u) ? (u & 0x7FFFFFFFu) : ~u);
}
__device__ __forceinline__ ull fma2(ull a, ull b, ull c) {
    ull d;
    asm("fma.rn.f32x2 %0, %1, %2, %3;" : "=l"(d) : "l"(a), "l"(b), "l"(c));
    return d;
}
__device__ __forceinline__ ull pack2(float x) {
    ull r;
    asm("mov.b64 %0, {%1, %1};" : "=l"(r) : "f"(x));
    return r;
}

// ---------------- kernel 1: per-row compaction metadata ----------------
__global__ __launch_bounds__(1024) void prep_kernel(
    const float* __restrict__ prev, const float* __restrict__ amask,
    float* __restrict__ out_mask)
{
    int b = blockIdx.x;
    int t = threadIdx.x;
    const float* pm = prev + b * S_;
    const float* am = amask + b * S_;

    int base_p = t * 4;
    float pv[4];
    int kept[4];
    int local = 0, lz = 0;
#pragma unroll
    for (int i = 0; i < 4; i++) {
        float v = pm[base_p + i];
        pv[i] = v;
        int k = (v > 0.5f) ? 1 : 0;
        kept[i] = k;
        local += k;
        lz += (k && (am[base_p + i] == 0.0f)) ? 1 : 0;
    }

    int lane = t & 31, warp = t >> 5;
    const unsigned FULL = 0xFFFFFFFFu;
    int inc = local;
#pragma unroll
    for (int o = 1; o < 32; o <<= 1) {
        int n = __shfl_up_sync(FULL, inc, o);
        if (lane >= o) inc += n;
    }
    int wz = lz;
#pragma unroll
    for (int o = 16; o > 0; o >>= 1) wz += __shfl_xor_sync(FULL, wz, o);

    __shared__ int wsum[32], wzsum[32], wbase[32];
    __shared__ int s_tot, s_cz;
    if (lane == 31) wsum[warp] = inc;
    if (lane == 0)  wzsum[warp] = wz;
    __syncthreads();
    if (t < 32) {
        int v = wsum[t];
        int e = v;
#pragma unroll
        for (int o = 1; o < 32; o <<= 1) {
            int n = __shfl_up_sync(FULL, e, o);
            if (t >= o) e += n;
        }
        wbase[t] = e - v;
        if (t == 31) s_tot = e;
        int z = wzsum[t];
#pragma unroll
        for (int o = 16; o > 0; o >>= 1) z += __shfl_xor_sync(FULL, z, o);
        if (t == 0) s_cz = z;
    }
    __syncthreads();

    int slot = wbase[warp] + inc - local;
#pragma unroll
    for (int i = 0; i < 4; i++) {
        int p = base_p + i;
        if (kept[i]) { g_pos[b * S_ + slot] = p; slot++; }
        out_mask[b * S_ + p] = kept[i] ? 0.0f : pv[i];
        g_smax[b * S_ + p] = 0u;
    }
    if (t == 0) {
        g_nb[b] = s_tot;
        float cz = (float)s_cz;
        int tk = (int)(cz * 0.8f);
        if (tk < 1) tk = 1;
        g_tokens[b] = tk;
    }
}

// ---------------- kernel 2: new_ret = hidden_states ----------------
__global__ void copy_kernel(const float4* __restrict__ src, float4* __restrict__ dst, int n4)
{
    int i = blockIdx.x * blockDim.x + threadIdx.x;
    int stride = gridDim.x * blockDim.x;
    for (; i < n4; i += stride) dst[i] = src[i];
}

// ---------------- kernel 3: gathered GEMM + row-max (f32x2 packed FMAs) ----------------
// Block tile: TM=128 tokens x TN=128 columns, K chunks of 16, 256 threads.
// Thread tile: 16 m (8 f32x2 pairs) x 4 n = 64 MACs per k via 32 FFMA2.
#define TM 128
#define TN 128
#define TK 16

__global__ __launch_bounds__(256) void gemm_kernel(
    const float* __restrict__ hmat, const float* __restrict__ W,
    const float* __restrict__ bias)
{
    int b = blockIdx.y;
    int nb = g_nb[b];
    int j0 = blockIdx.x * TM;
    if (j0 >= nb) return;
    int n0 = blockIdx.z * TN;

    int tid = threadIdx.x;
    int tx = tid & 31, ty = tid >> 5;   // ty = warp id (0..7), whole warp same ty

    __shared__ float As[2][TK][TM];
    __shared__ float Bs[2][TK][TN];
    __shared__ const float* rowptr_s[TM];

    if (tid < TM) {
        int j = j0 + tid;
        int jc = (j < nb) ? j : (nb - 1);
        if (jc < 0) jc = 0;
        int p = g_pos[b * S_ + jc];
        rowptr_s[tid] = hmat + ((size_t)b * S_ + (size_t)p) * H_;
    }
    __syncthreads();

    int am   = tid & 127;   // A row within tile
    int akq0 = tid >> 7;    // 0..1
    const float* wbase = W + n0;

    ull acc[8][4];
#pragma unroll
    for (int i = 0; i < 8; i++)
#pragma unroll
        for (int j = 0; j < 4; j++) acc[i][j] = 0ull;

    auto load_stage = [&](int stage, int kk) {
#pragma unroll
        for (int q = 0; q < 2; q++) {
            int akq = akq0 + q * 2;  // covers 0..3
            float4 av = *(const float4*)(rowptr_s[am] + kk + akq * 4);
            As[stage][akq * 4 + 0][am] = av.x;
            As[stage][akq * 4 + 1][am] = av.y;
            As[stage][akq * 4 + 2][am] = av.z;
            As[stage][akq * 4 + 3][am] = av.w;
        }
#pragma unroll
        for (int it = 0; it < 2; it++) {
            int idx = it * 256 + tid;
            int bk = idx >> 5;          // 0..15
            int bn = (idx & 31) * 4;    // 0..124
            float4 wv = *(const float4*)(wbase + (size_t)(kk + bk) * H_ + bn);
            *(float4*)&Bs[stage][bk][bn] = wv;
        }
    };

    load_stage(0, 0);
    __syncthreads();

#pragma unroll 1
    for (int kt = 0; kt < H_ / TK; kt++) {
        int cur = kt & 1;
        if (kt + 1 < H_ / TK) load_stage(cur ^ 1, (kt + 1) * TK);
#pragma unroll
        for (int k = 0; k < TK; k++) {
            const ull* ap = (const ull*)&As[cur][k][ty * 16];  // 8 natural (m,m+1) pairs
            ull a0 = ap[0], a1 = ap[1], a2 = ap[2], a3 = ap[3];
            ull a4 = ap[4], a5 = ap[5], a6 = ap[6], a7 = ap[7];
            float4 bw = *(const float4*)&Bs[cur][k][tx * 4];
            ull b0 = pack2(bw.x), b1 = pack2(bw.y), b2 = pack2(bw.z), b3 = pack2(bw.w);
            acc[0][0] = fma2(a0, b0, acc[0][0]);
            acc[1][0] = fma2(a1, b0, acc[1][0]);
            acc[2][0] = fma2(a2, b0, acc[2][0]);
            acc[3][0] = fma2(a3, b0, acc[3][0]);
            acc[4][0] = fma2(a4, b0, acc[4][0]);
            acc[5][0] = fma2(a5, b0, acc[5][0]);
            acc[6][0] = fma2(a6, b0, acc[6][0]);
            acc[7][0] = fma2(a7, b0, acc[7][0]);
            acc[0][1] = fma2(a0, b1, acc[0][1]);
            acc[1][1] = fma2(a1, b1, acc[1][1]);
            acc[2][1] = fma2(a2, b1, acc[2][1]);
            acc[3][1] = fma2(a3, b1, acc[3][1]);
            acc[4][1] = fma2(a4, b1, acc[4][1]);
            acc[5][1] = fma2(a5, b1, acc[5][1]);
            acc[6][1] = fma2(a6, b1, acc[6][1]);
            acc[7][1] = fma2(a7, b1, acc[7][1]);
            acc[0][2] = fma2(a0, b2, acc[0][2]);
            acc[1][2] = fma2(a1, b2, acc[1][2]);
            acc[2][2] = fma2(a2, b2, acc[2][2]);
            acc[3][2] = fma2(a3, b2, acc[3][2]);
            acc[4][2] = fma2(a4, b2, acc[4][2]);
            acc[5][2] = fma2(a5, b2, acc[5][2]);
            acc[6][2] = fma2(a6, b2, acc[6][2]);
            acc[7][2] = fma2(a7, b2, acc[7][2]);
            acc[0][3] = fma2(a0, b3, acc[0][3]);
            acc[1][3] = fma2(a1, b3, acc[1][3]);
            acc[2][3] = fma2(a2, b3, acc[2][3]);
            acc[3][3] = fma2(a3, b3, acc[3][3]);
            acc[4][3] = fma2(a4, b3, acc[4][3]);
            acc[5][3] = fma2(a5, b3, acc[5][3]);
            acc[6][3] = fma2(a6, b3, acc[6][3]);
            acc[7][3] = fma2(a7, b3, acc[7][3]);
        }
        __syncthreads();
    }

    // epilogue: add bias, per-row max over this block's 128 columns
    float rmax[16];
#pragma unroll
    for (int i = 0; i < 16; i++) rmax[i] = -3.0e38f;
#pragma unroll
    for (int jn = 0; jn < 4; jn++) {
        float bn = bias[n0 + tx * 4 + jn];
#pragma unroll
        for (int mi = 0; mi < 8; mi++) {
            float lo = __uint_as_float((unsigned)(acc[mi][jn] & 0xFFFFFFFFull)) + bn;
            float hi = __uint_as_float((unsigned)(acc[mi][jn] >> 32)) + bn;
            rmax[2 * mi]     = fmaxf(rmax[2 * mi], lo);
            rmax[2 * mi + 1] = fmaxf(rmax[2 * mi + 1], hi);
        }
    }
#pragma unroll
    for (int i = 0; i < 16; i++) {
        float v = rmax[i];
#pragma unroll
        for (int o = 16; o > 0; o >>= 1)
            v = fmaxf(v, __shfl_xor_sync(0xFFFFFFFFu, v, o));
        if (tx == 0) {
            int j = j0 + ty * 16 + i;
            if (j < nb) atomicMax(&g_smax[b * S_ + j], enc_f(v));
        }
    }
}

// ---------------- kernel 4: per-row top-k via radix select ----------------
// Keys are fully distinct (score-encoding | ~slot-index), so the top-tk set is
// exactly { key >= (tk-th largest key) } with no tie handling.
__global__ __launch_bounds__(1024) void topk_kernel(
    const float* __restrict__ amask, float* __restrict__ out_mask)
{
    int b = blockIdx.x;
    __shared__ ull skey[S_];
    __shared__ int hist[256];
    __shared__ ull s_pref;
    __shared__ int s_rank;
    int nb = g_nb[b];
    int tk = g_tokens[b];

    for (int j = threadIdx.x; j < S_; j += 1024) {
        ull kv = 0ull;
        if (j < nb) {
            float s = dec_f(g_smax[b * S_ + j]);
            int p = g_pos[b * S_ + j];
            float a = amask[b * S_ + p];
            float sv = s + a * 100.0f + a;
            kv = ((ull)enc_f(sv) << 32) | (ull)(0xFFFFFFFFu - (unsigned)j);
        }
        skey[j] = kv;
    }
    if (threadIdx.x == 0) { s_pref = 0ull; s_rank = tk; }
    __syncthreads();

    // 8 MSB->LSB radix passes to find the tk-th largest key exactly.
    for (int byte = 7; byte >= 0; byte--) {
        int sh = byte * 8;
        ull prefmask = (byte == 7) ? 0ull : (~0ull << (sh + 8));
        ull pref = s_pref;
        if (threadIdx.x < 256) hist[threadIdx.x] = 0;
        __syncthreads();
        for (int j = threadIdx.x; j < S_; j += 1024) {
            ull kv = skey[j];
            if ((kv & prefmask) == pref)
                atomicAdd(&hist[(int)((kv >> sh) & 0xFF)], 1);
        }
        __syncthreads();
        if (threadIdx.x == 0) {
            int rank = s_rank;
            int c = 0;
            for (int bb = 255; bb >= 0; bb--) {
                int h = hist[bb];
                if (c + h >= rank) {
                    s_pref = pref | ((ull)(unsigned)bb << sh);
                    s_rank = rank - c;
                    break;
                }
                c += h;
            }
        }
        __syncthreads();
    }

    ull thr = s_pref;  // the tk-th largest key (exact)
    for (int j = threadIdx.x; j < S_; j += 1024) {
        if (skey[j] >= thr) {
            int p = g_pos[b * S_ + j];
            out_mask[b * S_ + p] = 1.0f;
        }
    }
}

// ---------------- launch ----------------
extern "C" void kernel_launch(void* const* d_in, const int* in_sizes, int n_in,
                              void* d_out, int out_size)
{
    (void)in_sizes; (void)n_in; (void)out_size;
    const float* hidden = (const float*)d_in[0];
    const float* amask  = (const float*)d_in[1];
    const float* prev   = (const float*)d_in[2];
    const float* W      = (const float*)d_in[3];
    const float* bias   = (const float*)d_in[4];

    float* out_ret  = (float*)d_out;
    float* out_mask = out_ret + (size_t)B_ * S_ * H_;

    prep_kernel<<<B_, 1024>>>(prev, amask, out_mask);

    int n4 = B_ * S_ * H_ / 4;
    copy_kernel<<<4096, 512>>>((const float4*)hidden, (float4*)out_ret, n4);

    dim3 ggrid(S_ / TM, B_, H_ / TN);
    gemm_kernel<<<ggrid, 256>>>(hidden, W, bias);

    topk_kernel<<<B_, 1024>>>(amask, out_mask);
}